// round 2
// baseline (speedup 1.0000x reference)
#include <cuda_runtime.h>
#include <cuda_bf16.h>
#include <math.h>

#define NN 150000
#define NE 1250000
#define NG 4096
#define HID 64

// Scratch (allocation-free rule: __device__ globals)
__device__ __align__(256) float g_dinv[NN];
__device__ __align__(256) float g_A[NN * HID];   // t (post-linear) buffer
__device__ __align__(256) float g_B[NN * HID];   // h / agg buffer
__device__ __align__(256) float g_pool[NG * HID];
__device__ __align__(256) float g_cnt[NG];

__device__ __forceinline__ void red_add_v4(float* addr, float4 v) {
    asm volatile("red.global.add.v4.f32 [%0], {%1,%2,%3,%4};"
                 :: "l"(addr), "f"(v.x), "f"(v.y), "f"(v.z), "f"(v.w)
                 : "memory");
}

// ---------------- degree ----------------
__global__ void k_deg_init() {
    int i = blockIdx.x * blockDim.x + threadIdx.x;
    if (i < NN) g_dinv[i] = 1.0f;   // self loop
}

__global__ void k_deg_accum(const int* __restrict__ ei) {
    int e = blockIdx.x * blockDim.x + threadIdx.x;
    if (e < NE) atomicAdd(&g_dinv[ei[NE + e]], 1.0f);
}

__global__ void k_deg_fin() {
    int i = blockIdx.x * blockDim.x + threadIdx.x;
    if (i < NN) g_dinv[i] = rsqrtf(g_dinv[i]);
}

// ---------------- layer 1 linear (IN_CH=2) ----------------
// t = x @ W1 ; writes t -> g_A, self-loop init t*dinv^2 -> g_B
__global__ void k_lin_in(const float* __restrict__ x, const float* __restrict__ W) {
    int t = blockIdx.x * blockDim.x + threadIdx.x;
    if (t >= NN * HID) return;
    int i = t >> 6, c = t & 63;
    float v = x[2 * i] * W[c] + x[2 * i + 1] * W[HID + c];
    float di = g_dinv[i];
    g_A[t] = v;
    g_B[t] = v * di * di;
}

// ---------------- 64x64 linear ----------------
// t = hin @ W ; t -> outT, t*dinv^2 -> outAgg (outAgg may alias hin: safe,
// each block reads only its own 4 rows into shared before writing them back)
__global__ void k_lin64(const float* hin, const float* __restrict__ W,
                        float* outT, float* outAgg) {
    __shared__ float Ws[HID * HID];
    __shared__ float hs[4][HID];
    int tid = threadIdx.x;
    for (int idx = tid; idx < HID * HID; idx += 256) Ws[idx] = W[idx];
    int ni = tid >> 6, c = tid & 63;
    int node = blockIdx.x * 4 + ni;
    if (node < NN) hs[ni][c] = hin[node * HID + c];
    __syncthreads();
    if (node >= NN) return;
    float acc = 0.f;
#pragma unroll
    for (int k = 0; k < HID; k++) acc += hs[ni][k] * Ws[k * HID + c];
    float di = g_dinv[node];
    outT[node * HID + c]   = acc;
    outAgg[node * HID + c] = acc * di * di;
}

// ---------------- edge scatter ----------------
// 16 threads per edge, one float4 each. agg[dst] += t[src] * dinv[s]*dinv[d]
__global__ void k_edge(const int* __restrict__ ei,
                       const float* __restrict__ t, float* agg) {
    int gt = blockIdx.x * blockDim.x + threadIdx.x;
    int e = gt >> 4, q = gt & 15;
    if (e >= NE) return;
    int s = ei[e];
    int d = ei[NE + e];
    float coef = g_dinv[s] * g_dinv[d];
    float4 v = *(const float4*)(t + s * HID + q * 4);
    v.x *= coef; v.y *= coef; v.z *= coef; v.w *= coef;
    red_add_v4(agg + d * HID + q * 4, v);
}

// ---------------- bias + relu (in place) ----------------
__global__ void k_relu_bias(float* h, const float* __restrict__ b) {
    int t = blockIdx.x * blockDim.x + threadIdx.x;
    if (t >= NN * HID) return;
    float v = h[t] + b[t & 63];
    h[t] = v > 0.f ? v : 0.f;
}

// ---------------- pooling ----------------
__global__ void k_pool_init() {
    int i = blockIdx.x * blockDim.x + threadIdx.x;
    if (i < NG * HID) g_pool[i] = 0.f;
    else if (i < NG * HID + NG) g_cnt[i - NG * HID] = 0.f;
}

__global__ void k_pool(const int* __restrict__ batch, const float* __restrict__ h) {
    int gt = blockIdx.x * blockDim.x + threadIdx.x;
    int i = gt >> 4, q = gt & 15;
    if (i >= NN) return;
    int g = batch[i];
    float4 v = *(const float4*)(h + i * HID + q * 4);
    red_add_v4(g_pool + g * HID + q * 4, v);
    if (q == 0) atomicAdd(&g_cnt[g], 1.0f);
}

// ---------------- per-graph MLP + sigmoid ----------------
__global__ void k_mlp(const float* __restrict__ lw1, const float* __restrict__ lb1,
                      const float* __restrict__ lw2, const float* __restrict__ lb2,
                      float* __restrict__ out) {
    __shared__ float w1s[HID * 32];
    __shared__ float b1s[32];
    __shared__ float w2s[32];
    int tid = threadIdx.x;
    for (int idx = tid; idx < HID * 32; idx += 128) w1s[idx] = lw1[idx];
    if (tid < 32) { b1s[tid] = lb1[tid]; w2s[tid] = lw2[tid]; }
    __syncthreads();
    int g = blockIdx.x * 128 + tid;
    if (g >= NG) return;
    float inv = 1.0f / fmaxf(g_cnt[g], 1.0f);
    float p[HID];
#pragma unroll
    for (int c = 0; c < HID; c++) p[c] = g_pool[g * HID + c] * inv;
    float z = lb2[0];
    for (int j = 0; j < 32; j++) {
        float a = b1s[j];
#pragma unroll
        for (int c = 0; c < HID; c++) a += p[c] * w1s[c * 32 + j];
        a = a > 0.f ? a : 0.f;
        z += a * w2s[j];
    }
    out[g] = 1.0f / (1.0f + expf(-z));
}

extern "C" void kernel_launch(void* const* d_in, const int* in_sizes, int n_in,
                              void* d_out, int out_size) {
    // Size-driven input identification (robust to metadata ordering).
    const float *x = 0, *W1 = 0, *b1 = 0, *W2 = 0, *b2 = 0, *W3 = 0, *b3 = 0;
    const float *lw1 = 0, *lb1 = 0, *lw2 = 0, *lb2 = 0;
    const int *ei = 0, *batch = 0;
    int nW = 0, nb = 0, n32 = 0;
    for (int i = 0; i < n_in; i++) {
        int sz = in_sizes[i];
        const void* p = d_in[i];
        switch (sz) {
            case 300000:  x = (const float*)p; break;
            case 2500000: ei = (const int*)p; break;
            case 150000:  batch = (const int*)p; break;
            case 128:     W1 = (const float*)p; break;
            case 4096:    if (nW++ == 0) W2 = (const float*)p; else W3 = (const float*)p; break;
            case 64:      if (nb == 0) b1 = (const float*)p;
                          else if (nb == 1) b2 = (const float*)p;
                          else b3 = (const float*)p;
                          nb++; break;
            case 2048:    lw1 = (const float*)p; break;
            case 32:      if (n32++ == 0) lb1 = (const float*)p; else lw2 = (const float*)p; break;
            case 1:       lb2 = (const float*)p; break;
        }
    }
    float* out = (float*)d_out;

    float *gA, *gB;
    cudaGetSymbolAddress((void**)&gA, g_A);
    cudaGetSymbolAddress((void**)&gB, g_B);

    const int TB = 256;
    // degree
    k_deg_init <<<(NN + TB - 1) / TB, TB>>>();
    k_deg_accum<<<(NE + TB - 1) / TB, TB>>>(ei);
    k_deg_fin  <<<(NN + TB - 1) / TB, TB>>>();

    // layer 1: t->A, agg init->B, edges A->B, relu(B+b1)
    k_lin_in   <<<(NN * HID + TB - 1) / TB, TB>>>(x, W1);
    k_edge     <<<(NE * 16 + TB - 1) / TB, TB>>>(ei, gA, gB);
    k_relu_bias<<<(NN * HID + TB - 1) / TB, TB>>>(gB, b1);

    // layer 2: h in B -> t in A (+agg init into B), edges, relu
    k_lin64    <<<(NN + 3) / 4, TB>>>(gB, W2, gA, gB);
    k_edge     <<<(NE * 16 + TB - 1) / TB, TB>>>(ei, gA, gB);
    k_relu_bias<<<(NN * HID + TB - 1) / TB, TB>>>(gB, b2);

    // layer 3
    k_lin64    <<<(NN + 3) / 4, TB>>>(gB, W3, gA, gB);
    k_edge     <<<(NE * 16 + TB - 1) / TB, TB>>>(ei, gA, gB);
    k_relu_bias<<<(NN * HID + TB - 1) / TB, TB>>>(gB, b3);

    // pool + MLP
    k_pool_init<<<(NG * HID + NG + TB - 1) / TB, TB>>>();
    k_pool     <<<(NN * 16 + TB - 1) / TB, TB>>>(batch, gB);
    k_mlp      <<<(NG + 127) / 128, 128>>>(lw1, lb1, lw2, lb2, out);
}

// round 3
// speedup vs baseline: 1.3320x; 1.3320x over previous
#include <cuda_runtime.h>
#include <cuda_bf16.h>
#include <math.h>

#define NN 150000
#define NE 1250000
#define NG 4096
#define HID 64

#define PS_B 512
#define PS_NB ((NN + PS_B - 1) / PS_B)   // 293

// Scratch (__device__ globals; no allocation allowed)
__device__ __align__(256) float g_dinv[NN];
__device__ __align__(256) int   g_indeg[NN];
__device__ __align__(256) int   g_off[NN + 1];
__device__ __align__(256) int   g_cursor[NN];
__device__ __align__(256) int   g_bsum[PS_NB];
__device__ __align__(256) int2  g_edges[NE];     // {src, coef bits}, bucketed by dst
__device__ __align__(256) float g_A[NN * HID];   // t (post-linear)
__device__ __align__(256) float g_B[NN * HID];   // h
__device__ __align__(256) float g_pool[NG * HID];
__device__ __align__(256) float g_cnt[NG];

__device__ __forceinline__ void red_add_v4(float* addr, float4 v) {
    asm volatile("red.global.add.v4.f32 [%0], {%1,%2,%3,%4};"
                 :: "l"(addr), "f"(v.x), "f"(v.y), "f"(v.z), "f"(v.w)
                 : "memory");
}

// ---------------- degree ----------------
__global__ void k_deg_init() {
    int i = blockIdx.x * blockDim.x + threadIdx.x;
    if (i < NN) g_indeg[i] = 0;
}
__global__ void k_deg_accum(const int* __restrict__ ei) {
    int e = blockIdx.x * blockDim.x + threadIdx.x;
    if (e < NE) atomicAdd(&g_indeg[ei[NE + e]], 1);
}
__global__ void k_deg_fin() {
    int i = blockIdx.x * blockDim.x + threadIdx.x;
    if (i < NN) g_dinv[i] = rsqrtf((float)(g_indeg[i] + 1));
}

// ---------------- CSR build: block scan over in-degrees ----------------
__global__ void k_ps1() {
    __shared__ int sh[PS_B];
    int tid = threadIdx.x;
    int i = blockIdx.x * PS_B + tid;
    int v = (i < NN) ? g_indeg[i] : 0;
    sh[tid] = v;
    __syncthreads();
    for (int o = 1; o < PS_B; o <<= 1) {
        int t2 = (tid >= o) ? sh[tid - o] : 0;
        __syncthreads();
        sh[tid] += t2;
        __syncthreads();
    }
    if (i < NN) g_off[i] = sh[tid] - v;            // local exclusive
    if (tid == PS_B - 1) g_bsum[blockIdx.x] = sh[tid];
}
__global__ void k_ps2() {
    __shared__ int sh[PS_B];
    int tid = threadIdx.x;
    int v = (tid < PS_NB) ? g_bsum[tid] : 0;
    sh[tid] = v;
    __syncthreads();
    for (int o = 1; o < PS_B; o <<= 1) {
        int t2 = (tid >= o) ? sh[tid - o] : 0;
        __syncthreads();
        sh[tid] += t2;
        __syncthreads();
    }
    if (tid < PS_NB) g_bsum[tid] = sh[tid] - v;    // exclusive block offsets
}
__global__ void k_ps3() {
    int i = blockIdx.x * PS_B + threadIdx.x;
    if (i < NN) {
        int o = g_off[i] + g_bsum[blockIdx.x];
        g_off[i] = o;
        g_cursor[i] = o;
    }
    if (i == 0) g_off[NN] = NE;
}
__global__ void k_fill(const int* __restrict__ ei) {
    int e = blockIdx.x * blockDim.x + threadIdx.x;
    if (e >= NE) return;
    int s = ei[e];
    int d = ei[NE + e];
    float coef = g_dinv[s] * g_dinv[d];
    int pos = atomicAdd(&g_cursor[d], 1);
    g_edges[pos] = make_int2(s, __float_as_int(coef));
}

// ---------------- layer 1 linear (IN_CH=2): t = x @ W1 ----------------
__global__ void k_lin_in(const float* __restrict__ x, const float* __restrict__ W) {
    int t = blockIdx.x * blockDim.x + threadIdx.x;
    if (t >= NN * HID) return;
    int i = t >> 6, c = t & 63;
    g_A[t] = x[2 * i] * W[c] + x[2 * i + 1] * W[HID + c];
}

// ---------------- 64x64 linear: t = h @ W ----------------
__global__ void k_lin64(const float* __restrict__ hin, const float* __restrict__ W,
                        float* __restrict__ outT) {
    __shared__ float Ws[HID * HID];
    __shared__ float hs[4][HID];
    int tid = threadIdx.x;
    for (int idx = tid; idx < HID * HID; idx += 256) Ws[idx] = W[idx];
    int ni = tid >> 6, c = tid & 63;
    int node = blockIdx.x * 4 + ni;
    if (node < NN) hs[ni][c] = hin[node * HID + c];
    __syncthreads();
    if (node >= NN) return;
    float acc = 0.f;
#pragma unroll
    for (int k = 0; k < HID; k++) acc += hs[ni][k] * Ws[k * HID + c];
    outT[node * HID + c] = acc;
}

// ---------------- CSR aggregation + self-loop + bias + relu ----------------
// 16 lanes per node; lane q owns float4 chunk q. h[i] = relu(sum_in + t[i]*dinv^2 + b)
__global__ void k_aggr(const float* __restrict__ t, const float* __restrict__ b,
                       float* __restrict__ hout) {
    int gt = blockIdx.x * blockDim.x + threadIdx.x;
    int node = gt >> 4, q = gt & 15;
    if (node >= NN) return;
    float di = g_dinv[node];
    float4 acc = *(const float4*)(t + (size_t)node * HID + q * 4);
    float d2 = di * di;
    acc.x *= d2; acc.y *= d2; acc.z *= d2; acc.w *= d2;
    int beg = g_off[node], end = g_off[node + 1];
    for (int k = beg; k < end; k++) {
        int2 p = g_edges[k];
        float c = __int_as_float(p.y);
        float4 v = *(const float4*)(t + (size_t)p.x * HID + q * 4);
        acc.x += c * v.x; acc.y += c * v.y; acc.z += c * v.z; acc.w += c * v.w;
    }
    float4 bb = *(const float4*)(b + q * 4);
    acc.x = fmaxf(acc.x + bb.x, 0.f);
    acc.y = fmaxf(acc.y + bb.y, 0.f);
    acc.z = fmaxf(acc.z + bb.z, 0.f);
    acc.w = fmaxf(acc.w + bb.w, 0.f);
    *(float4*)(hout + (size_t)node * HID + q * 4) = acc;
}

// Layer-3 variant: epilogue goes straight into the mean-pool accumulators.
__global__ void k_aggr_pool(const float* __restrict__ t, const float* __restrict__ b,
                            const int* __restrict__ batch) {
    int gt = blockIdx.x * blockDim.x + threadIdx.x;
    int node = gt >> 4, q = gt & 15;
    if (node >= NN) return;
    float di = g_dinv[node];
    float4 acc = *(const float4*)(t + (size_t)node * HID + q * 4);
    float d2 = di * di;
    acc.x *= d2; acc.y *= d2; acc.z *= d2; acc.w *= d2;
    int beg = g_off[node], end = g_off[node + 1];
    for (int k = beg; k < end; k++) {
        int2 p = g_edges[k];
        float c = __int_as_float(p.y);
        float4 v = *(const float4*)(t + (size_t)p.x * HID + q * 4);
        acc.x += c * v.x; acc.y += c * v.y; acc.z += c * v.z; acc.w += c * v.w;
    }
    float4 bb = *(const float4*)(b + q * 4);
    acc.x = fmaxf(acc.x + bb.x, 0.f);
    acc.y = fmaxf(acc.y + bb.y, 0.f);
    acc.z = fmaxf(acc.z + bb.z, 0.f);
    acc.w = fmaxf(acc.w + bb.w, 0.f);
    int g = batch[node];
    red_add_v4(g_pool + (size_t)g * HID + q * 4, acc);
    if (q == 0) atomicAdd(&g_cnt[g], 1.0f);
}

// ---------------- pooling init ----------------
__global__ void k_pool_init() {
    int i = blockIdx.x * blockDim.x + threadIdx.x;
    if (i < NG * HID) g_pool[i] = 0.f;
    else if (i < NG * HID + NG) g_cnt[i - NG * HID] = 0.f;
}

// ---------------- per-graph MLP + sigmoid ----------------
__global__ void k_mlp(const float* __restrict__ lw1, const float* __restrict__ lb1,
                      const float* __restrict__ lw2, const float* __restrict__ lb2,
                      float* __restrict__ out) {
    __shared__ float w1s[HID * 32];
    __shared__ float b1s[32];
    __shared__ float w2s[32];
    int tid = threadIdx.x;
    for (int idx = tid; idx < HID * 32; idx += 128) w1s[idx] = lw1[idx];
    if (tid < 32) { b1s[tid] = lb1[tid]; w2s[tid] = lw2[tid]; }
    __syncthreads();
    int g = blockIdx.x * 128 + tid;
    if (g >= NG) return;
    float inv = 1.0f / fmaxf(g_cnt[g], 1.0f);
    float p[HID];
#pragma unroll
    for (int c = 0; c < HID; c++) p[c] = g_pool[g * HID + c] * inv;
    float z = lb2[0];
    for (int j = 0; j < 32; j++) {
        float a = b1s[j];
#pragma unroll
        for (int c = 0; c < HID; c++) a += p[c] * w1s[c * 32 + j];
        a = a > 0.f ? a : 0.f;
        z += a * w2s[j];
    }
    out[g] = 1.0f / (1.0f + expf(-z));
}

extern "C" void kernel_launch(void* const* d_in, const int* in_sizes, int n_in,
                              void* d_out, int out_size) {
    // Size-driven input identification (robust to metadata ordering).
    const float *x = 0, *W1 = 0, *b1 = 0, *W2 = 0, *b2 = 0, *W3 = 0, *b3 = 0;
    const float *lw1 = 0, *lb1 = 0, *lw2 = 0, *lb2 = 0;
    const int *ei = 0, *batch = 0;
    int nW = 0, nb = 0, n32 = 0;
    for (int i = 0; i < n_in; i++) {
        int sz = in_sizes[i];
        const void* p = d_in[i];
        switch (sz) {
            case 300000:  x = (const float*)p; break;
            case 2500000: ei = (const int*)p; break;
            case 150000:  batch = (const int*)p; break;
            case 128:     W1 = (const float*)p; break;
            case 4096:    if (nW++ == 0) W2 = (const float*)p; else W3 = (const float*)p; break;
            case 64:      if (nb == 0) b1 = (const float*)p;
                          else if (nb == 1) b2 = (const float*)p;
                          else b3 = (const float*)p;
                          nb++; break;
            case 2048:    lw1 = (const float*)p; break;
            case 32:      if (n32++ == 0) lb1 = (const float*)p; else lw2 = (const float*)p; break;
            case 1:       lb2 = (const float*)p; break;
        }
    }
    float* out = (float*)d_out;

    float *gA, *gB;
    cudaGetSymbolAddress((void**)&gA, g_A);
    cudaGetSymbolAddress((void**)&gB, g_B);

    const int TB = 256;
    // degree + dinv
    k_deg_init <<<(NN + TB - 1) / TB, TB>>>();
    k_deg_accum<<<(NE + TB - 1) / TB, TB>>>(ei);
    k_deg_fin  <<<(NN + TB - 1) / TB, TB>>>();

    // CSR build (dst-bucketed, packed {src, coef})
    k_ps1 <<<PS_NB, PS_B>>>();
    k_ps2 <<<1, PS_B>>>();
    k_ps3 <<<PS_NB, PS_B>>>();
    k_fill<<<(NE + TB - 1) / TB, TB>>>(ei);

    // pool init early (independent)
    k_pool_init<<<(NG * HID + NG + TB - 1) / TB, TB>>>();

    // layer 1
    k_lin_in<<<(NN * HID + TB - 1) / TB, TB>>>(x, W1);
    k_aggr  <<<(NN * 16 + TB - 1) / TB, TB>>>(gA, b1, gB);

    // layer 2
    k_lin64<<<(NN + 3) / 4, TB>>>(gB, W2, gA);
    k_aggr <<<(NN * 16 + TB - 1) / TB, TB>>>(gA, b2, gB);

    // layer 3 (fused into pooling)
    k_lin64    <<<(NN + 3) / 4, TB>>>(gB, W3, gA);
    k_aggr_pool<<<(NN * 16 + TB - 1) / TB, TB>>>(gA, b3, batch);

    // MLP head
    k_mlp<<<(NG + 127) / 128, 128>>>(lw1, lb1, lw2, lb2, out);
}

// round 5
// speedup vs baseline: 1.4631x; 1.0984x over previous
#include <cuda_runtime.h>
#include <cuda_fp16.h>
#include <math.h>

#define NN 150000
#define NE 1250000
#define NG 4096
#define HID 64

#define PS_B 512
#define PS_NB ((NN + PS_B - 1) / PS_B)   // 293

// Scratch (__device__ globals; no allocation allowed)
__device__ __align__(256) float  g_dinv[NN];
__device__ __align__(256) int    g_indeg[NN];
__device__ __align__(256) int    g_off[NN + 1];
__device__ __align__(256) int    g_cursor[NN];
__device__ __align__(256) int    g_bsum[PS_NB];
__device__ __align__(256) int2   g_edges[NE];     // {src, coef bits}, bucketed by dst
__device__ __align__(256) __half g_T[NN * HID];   // t (post-linear), fp16 gather operand
__device__ __align__(256) float  g_H[NN * HID];   // h (post-activation), fp32
__device__ __align__(256) float  g_pool[NG * HID];
__device__ __align__(256) float  g_cnt[NG];

__device__ __forceinline__ void red_add_v4(float* addr, float4 v) {
    asm volatile("red.global.add.v4.f32 [%0], {%1,%2,%3,%4};"
                 :: "l"(addr), "f"(v.x), "f"(v.y), "f"(v.z), "f"(v.w)
                 : "memory");
}

// ---------------- degree ----------------
__global__ void k_deg_init() {
    int i = blockIdx.x * blockDim.x + threadIdx.x;
    if (i < NN) g_indeg[i] = 0;
}
__global__ void k_deg_accum(const int* __restrict__ ei) {
    int e = blockIdx.x * blockDim.x + threadIdx.x;
    if (e < NE) atomicAdd(&g_indeg[ei[NE + e]], 1);
}
__global__ void k_deg_fin() {
    int i = blockIdx.x * blockDim.x + threadIdx.x;
    if (i < NN) g_dinv[i] = rsqrtf((float)(g_indeg[i] + 1));
}

// ---------------- CSR build: block scan over in-degrees ----------------
__global__ void k_ps1() {
    __shared__ int sh[PS_B];
    int tid = threadIdx.x;
    int i = blockIdx.x * PS_B + tid;
    int v = (i < NN) ? g_indeg[i] : 0;
    sh[tid] = v;
    __syncthreads();
    for (int o = 1; o < PS_B; o <<= 1) {
        int t2 = (tid >= o) ? sh[tid - o] : 0;
        __syncthreads();
        sh[tid] += t2;
        __syncthreads();
    }
    if (i < NN) g_off[i] = sh[tid] - v;            // local exclusive
    if (tid == PS_B - 1) g_bsum[blockIdx.x] = sh[tid];
}
__global__ void k_ps2() {
    __shared__ int sh[PS_B];
    int tid = threadIdx.x;
    int v = (tid < PS_NB) ? g_bsum[tid] : 0;
    sh[tid] = v;
    __syncthreads();
    for (int o = 1; o < PS_B; o <<= 1) {
        int t2 = (tid >= o) ? sh[tid - o] : 0;
        __syncthreads();
        sh[tid] += t2;
        __syncthreads();
    }
    if (tid < PS_NB) g_bsum[tid] = sh[tid] - v;    // exclusive block offsets
}
__global__ void k_ps3() {
    int i = blockIdx.x * PS_B + threadIdx.x;
    if (i < NN) {
        int o = g_off[i] + g_bsum[blockIdx.x];
        g_off[i] = o;
        g_cursor[i] = o;
    }
    if (i == 0) g_off[NN] = NE;
}
__global__ void k_fill(const int* __restrict__ ei) {
    int e = blockIdx.x * blockDim.x + threadIdx.x;
    if (e >= NE) return;
    int s = ei[e];
    int d = ei[NE + e];
    float coef = g_dinv[s] * g_dinv[d];
    int pos = atomicAdd(&g_cursor[d], 1);
    g_edges[pos] = make_int2(s, __float_as_int(coef));
}

// ---------------- layer 1: aggregate raw x (2ch), then fused W1+bias+relu ----------------
// 16 lanes per node; lanes split the edge list (contiguous => coalesced).
__global__ void k_aggr_x(const float* __restrict__ x, const float* __restrict__ W1,
                         const float* __restrict__ b1, float* __restrict__ hout) {
    __shared__ float W1s[2 * HID];
    __shared__ float b1s[HID];
    int tid = threadIdx.x;
    if (tid < 2 * HID) W1s[tid] = W1[tid];
    if (tid < HID) b1s[tid] = b1[tid];
    __syncthreads();
    int gt = blockIdx.x * blockDim.x + tid;
    int node = gt >> 4, q = gt & 15;
    if (node >= NN) return;
    int beg = __ldg(&g_off[node]), end = __ldg(&g_off[node + 1]);
    float s0 = 0.f, s1 = 0.f;
    for (int k = beg + q; k < end; k += 16) {
        int2 p = g_edges[k];
        float c = __int_as_float(p.y);
        float2 xv = *(const float2*)(x + 2 * p.x);
        s0 += c * xv.x; s1 += c * xv.y;
    }
#pragma unroll
    for (int o = 8; o; o >>= 1) {
        s0 += __shfl_xor_sync(0xffffffffu, s0, o, 16);
        s1 += __shfl_xor_sync(0xffffffffu, s1, o, 16);
    }
    float di = g_dinv[node];
    float d2 = di * di;
    s0 += x[2 * node] * d2;
    s1 += x[2 * node + 1] * d2;
    int c0 = q * 4;
    float4 r;
    r.x = fmaxf(s0 * W1s[c0 + 0] + s1 * W1s[HID + c0 + 0] + b1s[c0 + 0], 0.f);
    r.y = fmaxf(s0 * W1s[c0 + 1] + s1 * W1s[HID + c0 + 1] + b1s[c0 + 1], 0.f);
    r.z = fmaxf(s0 * W1s[c0 + 2] + s1 * W1s[HID + c0 + 2] + b1s[c0 + 2], 0.f);
    r.w = fmaxf(s0 * W1s[c0 + 3] + s1 * W1s[HID + c0 + 3] + b1s[c0 + 3], 0.f);
    *(float4*)(hout + (size_t)node * HID + c0) = r;
}

// ---------------- 64x64 linear: t = h @ W, fp16 output ----------------
__global__ void k_lin64h(const float* __restrict__ hin, const float* __restrict__ W,
                         __half* __restrict__ outT) {
    __shared__ float Ws[HID * HID];
    __shared__ float hs[4][HID];
    int tid = threadIdx.x;
    for (int idx = tid; idx < HID * HID; idx += 256) Ws[idx] = W[idx];
    int ni = tid >> 6, c = tid & 63;
    int node = blockIdx.x * 4 + ni;
    if (node < NN) hs[ni][c] = hin[(size_t)node * HID + c];
    __syncthreads();
    if (node >= NN) return;
    float acc = 0.f;
#pragma unroll
    for (int k = 0; k < HID; k++) acc += hs[ni][k] * Ws[k * HID + c];
    outT[(size_t)node * HID + c] = __float2half(acc);
}

// ---------------- CSR aggregation over fp16 t + self-loop + bias + relu ----------------
__device__ __forceinline__ float4 gather_h4(const __half* __restrict__ t, int row, int q) {
    uint2 raw = *(const uint2*)(t + ((size_t)row << 6) + (q << 2));
    float2 a = __half22float2(*(__half2*)&raw.x);
    float2 b = __half22float2(*(__half2*)&raw.y);
    return make_float4(a.x, a.y, b.x, b.y);
}

__global__ void k_aggr_h(const __half* __restrict__ t, const float* __restrict__ b,
                         float* __restrict__ hout) {
    int gt = blockIdx.x * blockDim.x + threadIdx.x;
    int node = gt >> 4, q = gt & 15;
    if (node >= NN) return;
    float di = g_dinv[node];
    float d2 = di * di;
    float4 acc = gather_h4(t, node, q);
    acc.x *= d2; acc.y *= d2; acc.z *= d2; acc.w *= d2;
    int beg = __ldg(&g_off[node]), end = __ldg(&g_off[node + 1]);
    for (int k = beg; k < end; k++) {
        int2 p = g_edges[k];
        float c = __int_as_float(p.y);
        float4 v = gather_h4(t, p.x, q);
        acc.x += c * v.x; acc.y += c * v.y; acc.z += c * v.z; acc.w += c * v.w;
    }
    float4 bb = *(const float4*)(b + q * 4);
    acc.x = fmaxf(acc.x + bb.x, 0.f);
    acc.y = fmaxf(acc.y + bb.y, 0.f);
    acc.z = fmaxf(acc.z + bb.z, 0.f);
    acc.w = fmaxf(acc.w + bb.w, 0.f);
    *(float4*)(hout + (size_t)node * HID + q * 4) = acc;
}

// Layer-3 variant: epilogue goes straight into the mean-pool accumulators.
__global__ void k_aggr_pool_h(const __half* __restrict__ t, const float* __restrict__ b,
                              const int* __restrict__ batch) {
    int gt = blockIdx.x * blockDim.x + threadIdx.x;
    int node = gt >> 4, q = gt & 15;
    if (node >= NN) return;
    float di = g_dinv[node];
    float d2 = di * di;
    float4 acc = gather_h4(t, node, q);
    acc.x *= d2; acc.y *= d2; acc.z *= d2; acc.w *= d2;
    int beg = __ldg(&g_off[node]), end = __ldg(&g_off[node + 1]);
    for (int k = beg; k < end; k++) {
        int2 p = g_edges[k];
        float c = __int_as_float(p.y);
        float4 v = gather_h4(t, p.x, q);
        acc.x += c * v.x; acc.y += c * v.y; acc.z += c * v.z; acc.w += c * v.w;
    }
    float4 bb = *(const float4*)(b + q * 4);
    acc.x = fmaxf(acc.x + bb.x, 0.f);
    acc.y = fmaxf(acc.y + bb.y, 0.f);
    acc.z = fmaxf(acc.z + bb.z, 0.f);
    acc.w = fmaxf(acc.w + bb.w, 0.f);
    int g = batch[node];
    red_add_v4(g_pool + (size_t)g * HID + q * 4, acc);
    if (q == 0) atomicAdd(&g_cnt[g], 1.0f);
}

// ---------------- pooling init ----------------
__global__ void k_pool_init() {
    int i = blockIdx.x * blockDim.x + threadIdx.x;
    if (i < NG * HID) g_pool[i] = 0.f;
    else if (i < NG * HID + NG) g_cnt[i - NG * HID] = 0.f;
}

// ---------------- per-graph MLP + sigmoid ----------------
__global__ void k_mlp(const float* __restrict__ lw1, const float* __restrict__ lb1,
                      const float* __restrict__ lw2, const float* __restrict__ lb2,
                      float* __restrict__ out) {
    __shared__ float w1s[HID * 32];
    __shared__ float b1s[32];
    __shared__ float w2s[32];
    int tid = threadIdx.x;
    for (int idx = tid; idx < HID * 32; idx += 128) w1s[idx] = lw1[idx];
    if (tid < 32) { b1s[tid] = lb1[tid]; w2s[tid] = lw2[tid]; }
    __syncthreads();
    int g = blockIdx.x * 128 + tid;
    if (g >= NG) return;
    float inv = 1.0f / fmaxf(g_cnt[g], 1.0f);
    float p[HID];
#pragma unroll
    for (int c = 0; c < HID; c++) p[c] = g_pool[g * HID + c] * inv;
    float z = lb2[0];
    for (int j = 0; j < 32; j++) {
        float a = b1s[j];
#pragma unroll
        for (int c = 0; c < HID; c++) a += p[c] * w1s[c * 32 + j];
        a = a > 0.f ? a : 0.f;
        z += a * w2s[j];
    }
    out[g] = 1.0f / (1.0f + expf(-z));
}

extern "C" void kernel_launch(void* const* d_in, const int* in_sizes, int n_in,
                              void* d_out, int out_size) {
    // Size-driven input identification (robust to metadata ordering).
    const float *x = 0, *W1 = 0, *b1 = 0, *W2 = 0, *b2 = 0, *W3 = 0, *b3 = 0;
    const float *lw1 = 0, *lb1 = 0, *lw2 = 0, *lb2 = 0;
    const int *ei = 0, *batch = 0;
    int nW = 0, nb = 0, n32 = 0;
    for (int i = 0; i < n_in; i++) {
        int sz = in_sizes[i];
        const void* p = d_in[i];
        switch (sz) {
            case 300000:  x = (const float*)p; break;
            case 2500000: ei = (const int*)p; break;
            case 150000:  batch = (const int*)p; break;
            case 128:     W1 = (const float*)p; break;
            case 4096:    if (nW++ == 0) W2 = (const float*)p; else W3 = (const float*)p; break;
            case 64:      if (nb == 0) b1 = (const float*)p;
                          else if (nb == 1) b2 = (const float*)p;
                          else b3 = (const float*)p;
                          nb++; break;
            case 2048:    lw1 = (const float*)p; break;
            case 32:      if (n32++ == 0) lb1 = (const float*)p; else lw2 = (const float*)p; break;
            case 1:       lb2 = (const float*)p; break;
        }
    }
    float* out = (float*)d_out;

    __half* gT;
    float*  gH;
    cudaGetSymbolAddress((void**)&gT, g_T);
    cudaGetSymbolAddress((void**)&gH, g_H);

    const int TB = 256;
    // degree + dinv
    k_deg_init <<<(NN + TB - 1) / TB, TB>>>();
    k_deg_accum<<<(NE + TB - 1) / TB, TB>>>(ei);
    k_deg_fin  <<<(NN + TB - 1) / TB, TB>>>();

    // CSR build (dst-bucketed, packed {src, coef})
    k_ps1 <<<PS_NB, PS_B>>>();
    k_ps2 <<<1, PS_B>>>();
    k_ps3 <<<PS_NB, PS_B>>>();
    k_fill<<<(NE + TB - 1) / TB, TB>>>(ei);

    // pool init early (independent)
    k_pool_init<<<(NG * HID + NG + TB - 1) / TB, TB>>>();

    // layer 1: aggregate raw x, fused W1+bias+relu -> h1 (fp32)
    k_aggr_x<<<(NN * 16 + TB - 1) / TB, TB>>>(x, W1, b1, gH);

    // layer 2: t2 = h1 @ W2 (fp16), aggregate -> h2 (fp32)
    k_lin64h<<<(NN + 3) / 4, TB>>>(gH, W2, gT);
    k_aggr_h<<<(NN * 16 + TB - 1) / TB, TB>>>(gT, b2, gH);

    // layer 3: t3 = h2 @ W3 (fp16), aggregate + pool
    k_lin64h    <<<(NN + 3) / 4, TB>>>(gH, W3, gT);
    k_aggr_pool_h<<<(NN * 16 + TB - 1) / TB, TB>>>(gT, b3, batch);

    // MLP head
    k_mlp<<<(NG + 127) / 128, 128>>>(lw1, lb1, lw2, lb2, out);
}

// round 7
// speedup vs baseline: 1.5192x; 1.0383x over previous
#include <cuda_runtime.h>
#include <cuda_fp16.h>
#include <math.h>

#define NN 150000
#define NE 1250000
#define NG 4096
#define HID 64

#define PS_B 512
#define PS_NB ((NN + PS_B - 1) / PS_B)   // 293

// Scratch (__device__ globals; no allocation allowed)
__device__ __align__(256) float  g_dinv[NN];
__device__ __align__(256) int    g_indeg[NN];
__device__ __align__(256) int    g_off[NN + 1];
__device__ __align__(256) int    g_cursor[NN];
__device__ __align__(256) int    g_bsum[PS_NB];
__device__ __align__(256) int2   g_edges[NE];     // {src, coef bits}, bucketed by dst
__device__ __align__(256) __half g_T[NN * HID];   // t (post-linear), fp16 gather operand
__device__ __align__(256) float  g_H[NN * HID];   // h (post-activation), fp32
__device__ __align__(256) float  g_pool[NG * HID];
__device__ __align__(256) float  g_cnt[NG];

__device__ __forceinline__ void red_add_v4(float* addr, float4 v) {
    asm volatile("red.global.add.v4.f32 [%0], {%1,%2,%3,%4};"
                 :: "l"(addr), "f"(v.x), "f"(v.y), "f"(v.z), "f"(v.w)
                 : "memory");
}

// ---------------- init (fused zeroing) ----------------
__global__ void k_init() {
    int i = blockIdx.x * blockDim.x + threadIdx.x;
    if (i < NN) g_indeg[i] = 0;
    if (i < NG * HID) g_pool[i] = 0.f;
    if (i < NG) g_cnt[i] = 0.f;
}

// ---------------- degree ----------------
__global__ void k_deg_accum(const int* __restrict__ ei) {
    int e = blockIdx.x * blockDim.x + threadIdx.x;
    if (e < NE) atomicAdd(&g_indeg[ei[NE + e]], 1);
}
__global__ void k_deg_fin() {
    int i = blockIdx.x * blockDim.x + threadIdx.x;
    if (i < NN) g_dinv[i] = rsqrtf((float)(g_indeg[i] + 1));
}

// ---------------- CSR build: block scan over in-degrees ----------------
__global__ void k_ps1() {
    __shared__ int sh[PS_B];
    int tid = threadIdx.x;
    int i = blockIdx.x * PS_B + tid;
    int v = (i < NN) ? g_indeg[i] : 0;
    sh[tid] = v;
    __syncthreads();
    for (int o = 1; o < PS_B; o <<= 1) {
        int t2 = (tid >= o) ? sh[tid - o] : 0;
        __syncthreads();
        sh[tid] += t2;
        __syncthreads();
    }
    if (i < NN) g_off[i] = sh[tid] - v;            // local exclusive
    if (tid == PS_B - 1) g_bsum[blockIdx.x] = sh[tid];
}
__global__ void k_ps2() {
    __shared__ int sh[PS_B];
    int tid = threadIdx.x;
    int v = (tid < PS_NB) ? g_bsum[tid] : 0;
    sh[tid] = v;
    __syncthreads();
    for (int o = 1; o < PS_B; o <<= 1) {
        int t2 = (tid >= o) ? sh[tid - o] : 0;
        __syncthreads();
        sh[tid] += t2;
        __syncthreads();
    }
    if (tid < PS_NB) g_bsum[tid] = sh[tid] - v;    // exclusive block offsets
}
__global__ void k_ps3() {
    int i = blockIdx.x * PS_B + threadIdx.x;
    if (i < NN) {
        int o = g_off[i] + g_bsum[blockIdx.x];
        g_off[i] = o;
        g_cursor[i] = o;
    }
    if (i == 0) g_off[NN] = NE;
}
__global__ void k_fill(const int* __restrict__ ei) {
    int e = blockIdx.x * blockDim.x + threadIdx.x;
    if (e >= NE) return;
    int s = ei[e];
    int d = ei[NE + e];
    float coef = g_dinv[s] * g_dinv[d];
    int pos = atomicAdd(&g_cursor[d], 1);
    g_edges[pos] = make_int2(s, __float_as_int(coef));
}

// ---------------- layer 1: aggregate raw x (2ch), then fused W1+bias+relu ----------------
// 16 lanes per node; lanes split the edge list (contiguous => coalesced). Unrolled x4.
__global__ void k_aggr_x(const float* __restrict__ x, const float* __restrict__ W1,
                         const float* __restrict__ b1, float* __restrict__ hout) {
    __shared__ float W1s[2 * HID];
    __shared__ float b1s[HID];
    int tid = threadIdx.x;
    if (tid < 2 * HID) W1s[tid] = W1[tid];
    if (tid < HID) b1s[tid] = b1[tid];
    __syncthreads();
    int gt = blockIdx.x * blockDim.x + tid;
    int node = gt >> 4, q = gt & 15;
    if (node >= NN) return;
    int beg = __ldg(&g_off[node]), end = __ldg(&g_off[node + 1]);
    float s0 = 0.f, s1 = 0.f;
    int k = beg + q;
    for (; k + 48 < end; k += 64) {
        int2 p0 = __ldg(&g_edges[k]);
        int2 p1 = __ldg(&g_edges[k + 16]);
        int2 p2 = __ldg(&g_edges[k + 32]);
        int2 p3 = __ldg(&g_edges[k + 48]);
        float2 x0 = *(const float2*)(x + 2 * p0.x);
        float2 x1 = *(const float2*)(x + 2 * p1.x);
        float2 x2 = *(const float2*)(x + 2 * p2.x);
        float2 x3 = *(const float2*)(x + 2 * p3.x);
        s0 += __int_as_float(p0.y) * x0.x; s1 += __int_as_float(p0.y) * x0.y;
        s0 += __int_as_float(p1.y) * x1.x; s1 += __int_as_float(p1.y) * x1.y;
        s0 += __int_as_float(p2.y) * x2.x; s1 += __int_as_float(p2.y) * x2.y;
        s0 += __int_as_float(p3.y) * x3.x; s1 += __int_as_float(p3.y) * x3.y;
    }
    for (; k < end; k += 16) {
        int2 p = __ldg(&g_edges[k]);
        float c = __int_as_float(p.y);
        float2 xv = *(const float2*)(x + 2 * p.x);
        s0 += c * xv.x; s1 += c * xv.y;
    }
#pragma unroll
    for (int o = 8; o; o >>= 1) {
        s0 += __shfl_xor_sync(0xffffffffu, s0, o, 16);
        s1 += __shfl_xor_sync(0xffffffffu, s1, o, 16);
    }
    float di = g_dinv[node];
    float d2 = di * di;
    s0 += x[2 * node] * d2;
    s1 += x[2 * node + 1] * d2;
    int c0 = q * 4;
    float4 r;
    r.x = fmaxf(s0 * W1s[c0 + 0] + s1 * W1s[HID + c0 + 0] + b1s[c0 + 0], 0.f);
    r.y = fmaxf(s0 * W1s[c0 + 1] + s1 * W1s[HID + c0 + 1] + b1s[c0 + 1], 0.f);
    r.z = fmaxf(s0 * W1s[c0 + 2] + s1 * W1s[HID + c0 + 2] + b1s[c0 + 2], 0.f);
    r.w = fmaxf(s0 * W1s[c0 + 3] + s1 * W1s[HID + c0 + 3] + b1s[c0 + 3], 0.f);
    *(float4*)(hout + (size_t)node * HID + c0) = r;
}

// ---------------- 64x64 linear: t = h @ W, fp16 output ----------------
__global__ void k_lin64h(const float* __restrict__ hin, const float* __restrict__ W,
                         __half* __restrict__ outT) {
    __shared__ float Ws[HID * HID];
    __shared__ float hs[4][HID];
    int tid = threadIdx.x;
    for (int idx = tid; idx < HID * HID; idx += 256) Ws[idx] = W[idx];
    int ni = tid >> 6, c = tid & 63;
    int node = blockIdx.x * 4 + ni;
    if (node < NN) hs[ni][c] = hin[(size_t)node * HID + c];
    __syncthreads();
    if (node >= NN) return;
    float acc = 0.f;
#pragma unroll
    for (int k = 0; k < HID; k++) acc += hs[ni][k] * Ws[k * HID + c];
    outT[(size_t)node * HID + c] = __float2half(acc);
}

// ---------------- CSR aggregation over fp16 t ----------------
__device__ __forceinline__ float4 gather_h4(const __half* __restrict__ t, int row, int q) {
    uint2 raw = __ldg((const uint2*)(t + ((size_t)row << 6) + (q << 2)));
    float2 a = __half22float2(*(__half2*)&raw.x);
    float2 b = __half22float2(*(__half2*)&raw.y);
    return make_float4(a.x, a.y, b.x, b.y);
}

// Shared body: accumulate self-loop + neighbors + bias + relu. Unrolled x4.
__device__ __forceinline__ float4 aggr_body(const __half* __restrict__ t,
                                            const float* __restrict__ b,
                                            int node, int q) {
    float di = g_dinv[node];
    float d2 = di * di;
    float4 acc = gather_h4(t, node, q);
    acc.x *= d2; acc.y *= d2; acc.z *= d2; acc.w *= d2;
    int beg = __ldg(&g_off[node]), end = __ldg(&g_off[node + 1]);
    int k = beg;
    for (; k + 4 <= end; k += 4) {
        int2 p0 = __ldg(&g_edges[k]);
        int2 p1 = __ldg(&g_edges[k + 1]);
        int2 p2 = __ldg(&g_edges[k + 2]);
        int2 p3 = __ldg(&g_edges[k + 3]);
        float4 v0 = gather_h4(t, p0.x, q);
        float4 v1 = gather_h4(t, p1.x, q);
        float4 v2 = gather_h4(t, p2.x, q);
        float4 v3 = gather_h4(t, p3.x, q);
        float c0 = __int_as_float(p0.y), c1 = __int_as_float(p1.y);
        float c2 = __int_as_float(p2.y), c3 = __int_as_float(p3.y);
        acc.x += c0 * v0.x; acc.y += c0 * v0.y; acc.z += c0 * v0.z; acc.w += c0 * v0.w;
        acc.x += c1 * v1.x; acc.y += c1 * v1.y; acc.z += c1 * v1.z; acc.w += c1 * v1.w;
        acc.x += c2 * v2.x; acc.y += c2 * v2.y; acc.z += c2 * v2.z; acc.w += c2 * v2.w;
        acc.x += c3 * v3.x; acc.y += c3 * v3.y; acc.z += c3 * v3.z; acc.w += c3 * v3.w;
    }
    for (; k < end; k++) {
        int2 p = __ldg(&g_edges[k]);
        float c = __int_as_float(p.y);
        float4 v = gather_h4(t, p.x, q);
        acc.x += c * v.x; acc.y += c * v.y; acc.z += c * v.z; acc.w += c * v.w;
    }
    float4 bb = *(const float4*)(b + q * 4);
    acc.x = fmaxf(acc.x + bb.x, 0.f);
    acc.y = fmaxf(acc.y + bb.y, 0.f);
    acc.z = fmaxf(acc.z + bb.z, 0.f);
    acc.w = fmaxf(acc.w + bb.w, 0.f);
    return acc;
}

__global__ void k_aggr_h(const __half* __restrict__ t, const float* __restrict__ b,
                         float* __restrict__ hout) {
    int gt = blockIdx.x * blockDim.x + threadIdx.x;
    int node = gt >> 4, q = gt & 15;
    if (node >= NN) return;
    float4 acc = aggr_body(t, b, node, q);
    *(float4*)(hout + (size_t)node * HID + q * 4) = acc;
}

// Layer-3 variant: epilogue goes straight into the mean-pool accumulators.
__global__ void k_aggr_pool_h(const __half* __restrict__ t, const float* __restrict__ b,
                              const int* __restrict__ batch) {
    int gt = blockIdx.x * blockDim.x + threadIdx.x;
    int node = gt >> 4, q = gt & 15;
    if (node >= NN) return;
    float4 acc = aggr_body(t, b, node, q);
    int g = batch[node];
    red_add_v4(g_pool + (size_t)g * HID + q * 4, acc);
    if (q == 0) atomicAdd(&g_cnt[g], 1.0f);
}

// ---------------- per-graph MLP + sigmoid ----------------
__global__ void k_mlp(const float* __restrict__ lw1, const float* __restrict__ lb1,
                      const float* __restrict__ lw2, const float* __restrict__ lb2,
                      float* __restrict__ out) {
    __shared__ float w1s[HID * 32];
    __shared__ float b1s[32];
    __shared__ float w2s[32];
    int tid = threadIdx.x;
    for (int idx = tid; idx < HID * 32; idx += 128) w1s[idx] = lw1[idx];
    if (tid < 32) { b1s[tid] = lb1[tid]; w2s[tid] = lw2[tid]; }
    __syncthreads();
    int g = blockIdx.x * 128 + tid;
    if (g >= NG) return;
    float inv = 1.0f / fmaxf(g_cnt[g], 1.0f);
    float p[HID];
#pragma unroll
    for (int c = 0; c < HID; c++) p[c] = g_pool[g * HID + c] * inv;
    float z = lb2[0];
    for (int j = 0; j < 32; j++) {
        float a = b1s[j];
#pragma unroll
        for (int c = 0; c < HID; c++) a += p[c] * w1s[c * 32 + j];
        a = a > 0.f ? a : 0.f;
        z += a * w2s[j];
    }
    out[g] = 1.0f / (1.0f + expf(-z));
}

extern "C" void kernel_launch(void* const* d_in, const int* in_sizes, int n_in,
                              void* d_out, int out_size) {
    // Size-driven input identification (robust to metadata ordering).
    const float *x = 0, *W1 = 0, *b1 = 0, *W2 = 0, *b2 = 0, *W3 = 0, *b3 = 0;
    const float *lw1 = 0, *lb1 = 0, *lw2 = 0, *lb2 = 0;
    const int *ei = 0, *batch = 0;
    int nW = 0, nb = 0, n32 = 0;
    for (int i = 0; i < n_in; i++) {
        int sz = in_sizes[i];
        const void* p = d_in[i];
        switch (sz) {
            case 300000:  x = (const float*)p; break;
            case 2500000: ei = (const int*)p; break;
            case 150000:  batch = (const int*)p; break;
            case 128:     W1 = (const float*)p; break;
            case 4096:    if (nW++ == 0) W2 = (const float*)p; else W3 = (const float*)p; break;
            case 64:      if (nb == 0) b1 = (const float*)p;
                          else if (nb == 1) b2 = (const float*)p;
                          else b3 = (const float*)p;
                          nb++; break;
            case 2048:    lw1 = (const float*)p; break;
            case 32:      if (n32++ == 0) lb1 = (const float*)p; else lw2 = (const float*)p; break;
            case 1:       lb2 = (const float*)p; break;
        }
    }
    float* out = (float*)d_out;

    __half* gT;
    float*  gH;
    cudaGetSymbolAddress((void**)&gT, g_T);
    cudaGetSymbolAddress((void**)&gH, g_H);

    const int TB = 256;
    // init + degree + dinv
    k_init     <<<(NG * HID + TB - 1) / TB, TB>>>();
    k_deg_accum<<<(NE + TB - 1) / TB, TB>>>(ei);
    k_deg_fin  <<<(NN + TB - 1) / TB, TB>>>();

    // CSR build (dst-bucketed, packed {src, coef})
    k_ps1 <<<PS_NB, PS_B>>>();
    k_ps2 <<<1, PS_B>>>();
    k_ps3 <<<PS_NB, PS_B>>>();
    k_fill<<<(NE + TB - 1) / TB, TB>>>(ei);

    // layer 1: aggregate raw x, fused W1+bias+relu -> h1 (fp32)
    k_aggr_x<<<(NN * 16 + TB - 1) / TB, TB>>>(x, W1, b1, gH);

    // layer 2: t2 = h1 @ W2 (fp16), aggregate -> h2 (fp32)
    k_lin64h<<<(NN + 3) / 4, TB>>>(gH, W2, gT);
    k_aggr_h<<<(NN * 16 + TB - 1) / TB, TB>>>(gT, b2, gH);

    // layer 3: t3 = h2 @ W3 (fp16), aggregate + pool
    k_lin64h     <<<(NN + 3) / 4, TB>>>(gH, W3, gT);
    k_aggr_pool_h<<<(NN * 16 + TB - 1) / TB, TB>>>(gT, b3, batch);

    // MLP head
    k_mlp<<<(NG + 127) / 128, 128>>>(lw1, lb1, lw2, lb2, out);
}

// round 8
// speedup vs baseline: 2.3888x; 1.5724x over previous
#include <cuda_runtime.h>
#include <cuda_fp16.h>
#include <math.h>

#define NN 150000
#define NE 1250000
#define NG 4096
#define HID 64

#define PS_B 512
#define PS_NB ((NN + PS_B - 1) / PS_B)   // 293

// Scratch (__device__ globals; no allocation allowed)
__device__ __align__(256) float  g_dinv[NN];
__device__ __align__(256) int    g_indeg[NN];
__device__ __align__(256) int    g_off[NN + 1];
__device__ __align__(256) int    g_cursor[NN];
__device__ __align__(256) int    g_bsum[PS_NB];
__device__ __align__(256) int2   g_edges[NE];     // {src, coef bits}, bucketed by dst
__device__ __align__(256) __half g_T0[NN * HID];  // h ping (fp16)
__device__ __align__(256) __half g_T1[NN * HID];  // h pong (fp16)
__device__ __align__(256) float  g_pool[NG * HID];
__device__ __align__(256) float  g_cnt[NG];

__device__ __forceinline__ void red_add_v4(float* addr, float4 v) {
    asm volatile("red.global.add.v4.f32 [%0], {%1,%2,%3,%4};"
                 :: "l"(addr), "f"(v.x), "f"(v.y), "f"(v.z), "f"(v.w)
                 : "memory");
}

// ---------------- init (fused zeroing) ----------------
__global__ void k_init() {
    int i = blockIdx.x * blockDim.x + threadIdx.x;
    if (i < NN) g_indeg[i] = 0;
    if (i < NG * HID) g_pool[i] = 0.f;
    if (i < NG) g_cnt[i] = 0.f;
}

// ---------------- degree ----------------
__global__ void k_deg_accum(const int* __restrict__ ei) {
    int e = blockIdx.x * blockDim.x + threadIdx.x;
    if (e < NE) atomicAdd(&g_indeg[ei[NE + e]], 1);
}
__global__ void k_deg_fin() {
    int i = blockIdx.x * blockDim.x + threadIdx.x;
    if (i < NN) g_dinv[i] = rsqrtf((float)(g_indeg[i] + 1));
}

// ---------------- CSR build: block scan over in-degrees ----------------
__global__ void k_ps1() {
    __shared__ int sh[PS_B];
    int tid = threadIdx.x;
    int i = blockIdx.x * PS_B + tid;
    int v = (i < NN) ? g_indeg[i] : 0;
    sh[tid] = v;
    __syncthreads();
    for (int o = 1; o < PS_B; o <<= 1) {
        int t2 = (tid >= o) ? sh[tid - o] : 0;
        __syncthreads();
        sh[tid] += t2;
        __syncthreads();
    }
    if (i < NN) g_off[i] = sh[tid] - v;            // local exclusive
    if (tid == PS_B - 1) g_bsum[blockIdx.x] = sh[tid];
}
__global__ void k_ps2() {
    __shared__ int sh[PS_B];
    int tid = threadIdx.x;
    int v = (tid < PS_NB) ? g_bsum[tid] : 0;
    sh[tid] = v;
    __syncthreads();
    for (int o = 1; o < PS_B; o <<= 1) {
        int t2 = (tid >= o) ? sh[tid - o] : 0;
        __syncthreads();
        sh[tid] += t2;
        __syncthreads();
    }
    if (tid < PS_NB) g_bsum[tid] = sh[tid] - v;    // exclusive block offsets
}
__global__ void k_ps3() {
    int i = blockIdx.x * PS_B + threadIdx.x;
    if (i < NN) {
        int o = g_off[i] + g_bsum[blockIdx.x];
        g_off[i] = o;
        g_cursor[i] = o;
    }
    if (i == 0) g_off[NN] = NE;
}
__global__ void k_fill(const int* __restrict__ ei) {
    int e = blockIdx.x * blockDim.x + threadIdx.x;
    if (e >= NE) return;
    int s = ei[e];
    int d = ei[NE + e];
    float coef = g_dinv[s] * g_dinv[d];
    int pos = atomicAdd(&g_cursor[d], 1);
    g_edges[pos] = make_int2(s, __float_as_int(coef));
}

// ---------------- store 4 fp32 as 4 fp16 (8B) ----------------
__device__ __forceinline__ void store_h4(__half* dst, float4 v) {
    __half2 lo = __floats2half2_rn(v.x, v.y);
    __half2 hi = __floats2half2_rn(v.z, v.w);
    uint2 raw;
    raw.x = *(unsigned*)&lo;
    raw.y = *(unsigned*)&hi;
    *(uint2*)dst = raw;
}

// ---------------- layer 1: aggregate raw x (2ch), fused W1+bias+relu -> fp16 ----------------
// 16 lanes per node; lanes split the edge list (contiguous => coalesced). Unrolled x4.
__global__ void k_aggr_x(const float* __restrict__ x, const float* __restrict__ W1,
                         const float* __restrict__ b1, __half* __restrict__ hout) {
    __shared__ float W1s[2 * HID];
    __shared__ float b1s[HID];
    int tid = threadIdx.x;
    if (tid < 2 * HID) W1s[tid] = W1[tid];
    if (tid < HID) b1s[tid] = b1[tid];
    __syncthreads();
    int gt = blockIdx.x * blockDim.x + tid;
    int node = gt >> 4, q = gt & 15;
    if (node >= NN) return;
    int beg = __ldg(&g_off[node]), end = __ldg(&g_off[node + 1]);
    float s0 = 0.f, s1 = 0.f;
    int k = beg + q;
    for (; k + 48 < end; k += 64) {
        int2 p0 = __ldg(&g_edges[k]);
        int2 p1 = __ldg(&g_edges[k + 16]);
        int2 p2 = __ldg(&g_edges[k + 32]);
        int2 p3 = __ldg(&g_edges[k + 48]);
        float2 x0 = *(const float2*)(x + 2 * p0.x);
        float2 x1 = *(const float2*)(x + 2 * p1.x);
        float2 x2 = *(const float2*)(x + 2 * p2.x);
        float2 x3 = *(const float2*)(x + 2 * p3.x);
        s0 += __int_as_float(p0.y) * x0.x; s1 += __int_as_float(p0.y) * x0.y;
        s0 += __int_as_float(p1.y) * x1.x; s1 += __int_as_float(p1.y) * x1.y;
        s0 += __int_as_float(p2.y) * x2.x; s1 += __int_as_float(p2.y) * x2.y;
        s0 += __int_as_float(p3.y) * x3.x; s1 += __int_as_float(p3.y) * x3.y;
    }
    for (; k < end; k += 16) {
        int2 p = __ldg(&g_edges[k]);
        float c = __int_as_float(p.y);
        float2 xv = *(const float2*)(x + 2 * p.x);
        s0 += c * xv.x; s1 += c * xv.y;
    }
#pragma unroll
    for (int o = 8; o; o >>= 1) {
        s0 += __shfl_xor_sync(0xffffffffu, s0, o, 16);
        s1 += __shfl_xor_sync(0xffffffffu, s1, o, 16);
    }
    float di = g_dinv[node];
    float d2 = di * di;
    s0 += x[2 * node] * d2;
    s1 += x[2 * node + 1] * d2;
    int c0 = q * 4;
    float4 r;
    r.x = fmaxf(s0 * W1s[c0 + 0] + s1 * W1s[HID + c0 + 0] + b1s[c0 + 0], 0.f);
    r.y = fmaxf(s0 * W1s[c0 + 1] + s1 * W1s[HID + c0 + 1] + b1s[c0 + 1], 0.f);
    r.z = fmaxf(s0 * W1s[c0 + 2] + s1 * W1s[HID + c0 + 2] + b1s[c0 + 2], 0.f);
    r.w = fmaxf(s0 * W1s[c0 + 3] + s1 * W1s[HID + c0 + 3] + b1s[c0 + 3], 0.f);
    store_h4(hout + (size_t)node * HID + c0, r);
}

// ---------------- fp16 row gather ----------------
__device__ __forceinline__ float4 gather_h4(const __half* __restrict__ t, int row, int q) {
    uint2 raw = __ldg((const uint2*)(t + ((size_t)row << 6) + (q << 2)));
    float2 a = __half22float2(*(__half2*)&raw.x);
    float2 b = __half22float2(*(__half2*)&raw.y);
    return make_float4(a.x, a.y, b.x, b.y);
}

// Aggregation core: u = agg_edges(h) + h[node]*dinv^2, per-lane float4 chunk.
__device__ __forceinline__ float4 agg_core(const __half* __restrict__ t, int node, int q) {
    float di = g_dinv[node];
    float d2 = di * di;
    float4 acc = gather_h4(t, node, q);
    acc.x *= d2; acc.y *= d2; acc.z *= d2; acc.w *= d2;
    int beg = __ldg(&g_off[node]), end = __ldg(&g_off[node + 1]);
    int k = beg;
    for (; k + 4 <= end; k += 4) {
        int2 p0 = __ldg(&g_edges[k]);
        int2 p1 = __ldg(&g_edges[k + 1]);
        int2 p2 = __ldg(&g_edges[k + 2]);
        int2 p3 = __ldg(&g_edges[k + 3]);
        float4 v0 = gather_h4(t, p0.x, q);
        float4 v1 = gather_h4(t, p1.x, q);
        float4 v2 = gather_h4(t, p2.x, q);
        float4 v3 = gather_h4(t, p3.x, q);
        float c0 = __int_as_float(p0.y), c1 = __int_as_float(p1.y);
        float c2 = __int_as_float(p2.y), c3 = __int_as_float(p3.y);
        acc.x += c0 * v0.x; acc.y += c0 * v0.y; acc.z += c0 * v0.z; acc.w += c0 * v0.w;
        acc.x += c1 * v1.x; acc.y += c1 * v1.y; acc.z += c1 * v1.z; acc.w += c1 * v1.w;
        acc.x += c2 * v2.x; acc.y += c2 * v2.y; acc.z += c2 * v2.z; acc.w += c2 * v2.w;
        acc.x += c3 * v3.x; acc.y += c3 * v3.y; acc.z += c3 * v3.z; acc.w += c3 * v3.w;
    }
    for (; k < end; k++) {
        int2 p = __ldg(&g_edges[k]);
        float c = __int_as_float(p.y);
        float4 v = gather_h4(t, p.x, q);
        acc.x += c * v.x; acc.y += c * v.y; acc.z += c * v.z; acc.w += c * v.w;
    }
    return acc;
}

// ---------------- fused layer: out = relu((agg(h) + h*dinv^2) @ W + b) ----------------
// 256 threads = 16 nodes x 16 lanes. Aggregate into smem, then in-block 64x64 matmul.
#define LPAD 68
__global__ void k_layer(const __half* __restrict__ tin, const float* __restrict__ W,
                        const float* __restrict__ b, __half* __restrict__ tout) {
    __shared__ float Ws[HID * HID];
    __shared__ float bs[HID];
    __shared__ float hs[16][LPAD];
    int tid = threadIdx.x;
    for (int i = tid; i < HID * HID; i += 256) Ws[i] = W[i];
    if (tid < HID) bs[tid] = b[tid];
    int ni = tid >> 4, q = tid & 15;
    int node = blockIdx.x * 16 + ni;
    if (node < NN) {
        float4 acc = agg_core(tin, node, q);
        *(float4*)&hs[ni][q * 4] = acc;
    }
    __syncthreads();
    if (node >= NN) return;
    int c0 = q * 4;
    float4 o = make_float4(bs[c0], bs[c0 + 1], bs[c0 + 2], bs[c0 + 3]);
#pragma unroll 16
    for (int k = 0; k < HID; k++) {
        float hk = hs[ni][k];
        float4 w = *(const float4*)&Ws[k * HID + c0];
        o.x += hk * w.x; o.y += hk * w.y; o.z += hk * w.z; o.w += hk * w.w;
    }
    o.x = fmaxf(o.x, 0.f); o.y = fmaxf(o.y, 0.f);
    o.z = fmaxf(o.z, 0.f); o.w = fmaxf(o.w, 0.f);
    store_h4(tout + (size_t)node * HID + c0, o);
}

// Layer-3 variant: epilogue goes straight into the mean-pool accumulators.
__global__ void k_layer_pool(const __half* __restrict__ tin, const float* __restrict__ W,
                             const float* __restrict__ b, const int* __restrict__ batch) {
    __shared__ float Ws[HID * HID];
    __shared__ float bs[HID];
    __shared__ float hs[16][LPAD];
    int tid = threadIdx.x;
    for (int i = tid; i < HID * HID; i += 256) Ws[i] = W[i];
    if (tid < HID) bs[tid] = b[tid];
    int ni = tid >> 4, q = tid & 15;
    int node = blockIdx.x * 16 + ni;
    if (node < NN) {
        float4 acc = agg_core(tin, node, q);
        *(float4*)&hs[ni][q * 4] = acc;
    }
    __syncthreads();
    if (node >= NN) return;
    int c0 = q * 4;
    float4 o = make_float4(bs[c0], bs[c0 + 1], bs[c0 + 2], bs[c0 + 3]);
#pragma unroll 16
    for (int k = 0; k < HID; k++) {
        float hk = hs[ni][k];
        float4 w = *(const float4*)&Ws[k * HID + c0];
        o.x += hk * w.x; o.y += hk * w.y; o.z += hk * w.z; o.w += hk * w.w;
    }
    o.x = fmaxf(o.x, 0.f); o.y = fmaxf(o.y, 0.f);
    o.z = fmaxf(o.z, 0.f); o.w = fmaxf(o.w, 0.f);
    int g = batch[node];
    red_add_v4(g_pool + (size_t)g * HID + c0, o);
    if (q == 0) atomicAdd(&g_cnt[g], 1.0f);
}

// ---------------- per-graph MLP + sigmoid ----------------
__global__ void k_mlp(const float* __restrict__ lw1, const float* __restrict__ lb1,
                      const float* __restrict__ lw2, const float* __restrict__ lb2,
                      float* __restrict__ out) {
    __shared__ float w1s[HID * 32];
    __shared__ float b1s[32];
    __shared__ float w2s[32];
    int tid = threadIdx.x;
    for (int idx = tid; idx < HID * 32; idx += 128) w1s[idx] = lw1[idx];
    if (tid < 32) { b1s[tid] = lb1[tid]; w2s[tid] = lw2[tid]; }
    __syncthreads();
    int g = blockIdx.x * 128 + tid;
    if (g >= NG) return;
    float inv = 1.0f / fmaxf(g_cnt[g], 1.0f);
    float p[HID];
#pragma unroll
    for (int c = 0; c < HID; c++) p[c] = g_pool[g * HID + c] * inv;
    float z = lb2[0];
    for (int j = 0; j < 32; j++) {
        float a = b1s[j];
#pragma unroll
        for (int c = 0; c < HID; c++) a += p[c] * w1s[c * 32 + j];
        a = a > 0.f ? a : 0.f;
        z += a * w2s[j];
    }
    out[g] = 1.0f / (1.0f + expf(-z));
}

extern "C" void kernel_launch(void* const* d_in, const int* in_sizes, int n_in,
                              void* d_out, int out_size) {
    // Size-driven input identification (robust to metadata ordering).
    const float *x = 0, *W1 = 0, *b1 = 0, *W2 = 0, *b2 = 0, *W3 = 0, *b3 = 0;
    const float *lw1 = 0, *lb1 = 0, *lw2 = 0, *lb2 = 0;
    const int *ei = 0, *batch = 0;
    int nW = 0, nb = 0, n32 = 0;
    for (int i = 0; i < n_in; i++) {
        int sz = in_sizes[i];
        const void* p = d_in[i];
        switch (sz) {
            case 300000:  x = (const float*)p; break;
            case 2500000: ei = (const int*)p; break;
            case 150000:  batch = (const int*)p; break;
            case 128:     W1 = (const float*)p; break;
            case 4096:    if (nW++ == 0) W2 = (const float*)p; else W3 = (const float*)p; break;
            case 64:      if (nb == 0) b1 = (const float*)p;
                          else if (nb == 1) b2 = (const float*)p;
                          else b3 = (const float*)p;
                          nb++; break;
            case 2048:    lw1 = (const float*)p; break;
            case 32:      if (n32++ == 0) lb1 = (const float*)p; else lw2 = (const float*)p; break;
            case 1:       lb2 = (const float*)p; break;
        }
    }
    float* out = (float*)d_out;

    __half *gT0, *gT1;
    cudaGetSymbolAddress((void**)&gT0, g_T0);
    cudaGetSymbolAddress((void**)&gT1, g_T1);

    const int TB = 256;
    // init + degree + dinv
    k_init     <<<(NG * HID + TB - 1) / TB, TB>>>();
    k_deg_accum<<<(NE + TB - 1) / TB, TB>>>(ei);
    k_deg_fin  <<<(NN + TB - 1) / TB, TB>>>();

    // CSR build (dst-bucketed, packed {src, coef})
    k_ps1 <<<PS_NB, PS_B>>>();
    k_ps2 <<<1, PS_B>>>();
    k_ps3 <<<PS_NB, PS_B>>>();
    k_fill<<<(NE + TB - 1) / TB, TB>>>(ei);

    // layer 1: aggregate raw x, fused W1+bias+relu -> h1 (fp16)
    k_aggr_x<<<(NN * 16 + TB - 1) / TB, TB>>>(x, W1, b1, gT0);

    // layer 2 fused: h2 = relu((agg(h1)+h1*d2) @ W2 + b2) (fp16)
    k_layer<<<(NN + 15) / 16, TB>>>(gT0, W2, b2, gT1);

    // layer 3 fused + pooled
    k_layer_pool<<<(NN + 15) / 16, TB>>>(gT1, W3, b3, batch);

    // MLP head
    k_mlp<<<(NG + 127) / 128, 128>>>(lw1, lb1, lw2, lb2, out);
}

// round 10
// speedup vs baseline: 2.4249x; 1.0151x over previous
#include <cuda_runtime.h>
#include <cuda_fp16.h>
#include <math.h>

#define NN 150000
#define NE 1250000
#define NG 4096
#define HID 64

#define PS_B 512
#define PS_NB ((NN + PS_B - 1) / PS_B)   // 293

// Scratch (__device__ globals; no allocation allowed)
__device__ __align__(256) float  g_dinv[NN];
__device__ __align__(256) int    g_indeg[NN];
__device__ __align__(256) int    g_off[NN + 1];
__device__ __align__(256) int    g_cursor[NN];
__device__ __align__(256) int    g_bsum[PS_NB];
__device__ __align__(256) int2   g_edges[NE];     // {src, coef bits}, bucketed by dst
__device__ __align__(256) __half g_T0[NN * HID];  // h ping (fp16)
__device__ __align__(256) __half g_T1[NN * HID];  // h pong (fp16)
__device__ __align__(256) float  g_pool[NG * HID];
__device__ __align__(256) float  g_cnt[NG];

__device__ __forceinline__ void red_add_v4(float* addr, float4 v) {
    asm volatile("red.global.add.v4.f32 [%0], {%1,%2,%3,%4};"
                 :: "l"(addr), "f"(v.x), "f"(v.y), "f"(v.z), "f"(v.w)
                 : "memory");
}

// ---------------- init (fused zeroing) ----------------
__global__ void k_init() {
    int i = blockIdx.x * blockDim.x + threadIdx.x;
    if (i < NN) g_indeg[i] = 0;
    if (i < NG * HID) g_pool[i] = 0.f;
    if (i < NG) g_cnt[i] = 0.f;
}

// ---------------- degree ----------------
__global__ void k_deg_accum(const int* __restrict__ ei) {
    int e = blockIdx.x * blockDim.x + threadIdx.x;
    if (e < NE) atomicAdd(&g_indeg[ei[NE + e]], 1);
}

// ---------------- CSR build: block scan over in-degrees (+dinv fused) ----------------
__global__ void k_ps1() {
    __shared__ int sh[PS_B];
    int tid = threadIdx.x;
    int i = blockIdx.x * PS_B + tid;
    int v = (i < NN) ? g_indeg[i] : 0;
    if (i < NN) g_dinv[i] = rsqrtf((float)(v + 1));   // fused deg_fin
    sh[tid] = v;
    __syncthreads();
    for (int o = 1; o < PS_B; o <<= 1) {
        int t2 = (tid >= o) ? sh[tid - o] : 0;
        __syncthreads();
        sh[tid] += t2;
        __syncthreads();
    }
    if (i < NN) g_off[i] = sh[tid] - v;            // local exclusive
    if (tid == PS_B - 1) g_bsum[blockIdx.x] = sh[tid];
}
__global__ void k_ps2() {
    __shared__ int sh[PS_B];
    int tid = threadIdx.x;
    int v = (tid < PS_NB) ? g_bsum[tid] : 0;
    sh[tid] = v;
    __syncthreads();
    for (int o = 1; o < PS_B; o <<= 1) {
        int t2 = (tid >= o) ? sh[tid - o] : 0;
        __syncthreads();
        sh[tid] += t2;
        __syncthreads();
    }
    if (tid < PS_NB) g_bsum[tid] = sh[tid] - v;    // exclusive block offsets
}
__global__ void k_ps3() {
    int i = blockIdx.x * PS_B + threadIdx.x;
    if (i < NN) {
        int o = g_off[i] + g_bsum[blockIdx.x];
        g_off[i] = o;
        g_cursor[i] = o;
    }
    if (i == 0) g_off[NN] = NE;
}
__global__ void k_fill(const int* __restrict__ ei) {
    int e = blockIdx.x * blockDim.x + threadIdx.x;
    if (e >= NE) return;
    int s = ei[e];
    int d = ei[NE + e];
    float coef = g_dinv[s] * g_dinv[d];
    int pos = atomicAdd(&g_cursor[d], 1);
    g_edges[pos] = make_int2(s, __float_as_int(coef));
}

// ---------------- store 4 fp32 as 4 fp16 (8B) ----------------
__device__ __forceinline__ void store_h4(__half* dst, float4 v) {
    __half2 lo = __floats2half2_rn(v.x, v.y);
    __half2 hi = __floats2half2_rn(v.z, v.w);
    uint2 raw;
    raw.x = *(unsigned*)&lo;
    raw.y = *(unsigned*)&hi;
    *(uint2*)dst = raw;
}

// ---------------- layer 1: aggregate raw x (2ch), fused W1+bias+relu -> fp16 ----------------
__global__ void k_aggr_x(const float* __restrict__ x, const float* __restrict__ W1,
                         const float* __restrict__ b1, __half* __restrict__ hout) {
    __shared__ float W1s[2 * HID];
    __shared__ float b1s[HID];
    int tid = threadIdx.x;
    if (tid < 2 * HID) W1s[tid] = W1[tid];
    if (tid < HID) b1s[tid] = b1[tid];
    __syncthreads();
    int gt = blockIdx.x * blockDim.x + tid;
    int node = gt >> 4, q = gt & 15;
    if (node >= NN) return;
    int beg = __ldg(&g_off[node]), end = __ldg(&g_off[node + 1]);
    float s0 = 0.f, s1 = 0.f;
    int k = beg + q;
    for (; k + 48 < end; k += 64) {
        int2 p0 = __ldg(&g_edges[k]);
        int2 p1 = __ldg(&g_edges[k + 16]);
        int2 p2 = __ldg(&g_edges[k + 32]);
        int2 p3 = __ldg(&g_edges[k + 48]);
        float2 x0 = *(const float2*)(x + 2 * p0.x);
        float2 x1 = *(const float2*)(x + 2 * p1.x);
        float2 x2 = *(const float2*)(x + 2 * p2.x);
        float2 x3 = *(const float2*)(x + 2 * p3.x);
        s0 += __int_as_float(p0.y) * x0.x; s1 += __int_as_float(p0.y) * x0.y;
        s0 += __int_as_float(p1.y) * x1.x; s1 += __int_as_float(p1.y) * x1.y;
        s0 += __int_as_float(p2.y) * x2.x; s1 += __int_as_float(p2.y) * x2.y;
        s0 += __int_as_float(p3.y) * x3.x; s1 += __int_as_float(p3.y) * x3.y;
    }
    for (; k < end; k += 16) {
        int2 p = __ldg(&g_edges[k]);
        float c = __int_as_float(p.y);
        float2 xv = *(const float2*)(x + 2 * p.x);
        s0 += c * xv.x; s1 += c * xv.y;
    }
#pragma unroll
    for (int o = 8; o; o >>= 1) {
        s0 += __shfl_xor_sync(0xffffffffu, s0, o, 16);
        s1 += __shfl_xor_sync(0xffffffffu, s1, o, 16);
    }
    float di = g_dinv[node];
    float d2 = di * di;
    s0 += x[2 * node] * d2;
    s1 += x[2 * node + 1] * d2;
    int c0 = q * 4;
    float4 r;
    r.x = fmaxf(s0 * W1s[c0 + 0] + s1 * W1s[HID + c0 + 0] + b1s[c0 + 0], 0.f);
    r.y = fmaxf(s0 * W1s[c0 + 1] + s1 * W1s[HID + c0 + 1] + b1s[c0 + 1], 0.f);
    r.z = fmaxf(s0 * W1s[c0 + 2] + s1 * W1s[HID + c0 + 2] + b1s[c0 + 2], 0.f);
    r.w = fmaxf(s0 * W1s[c0 + 3] + s1 * W1s[HID + c0 + 3] + b1s[c0 + 3], 0.f);
    store_h4(hout + (size_t)node * HID + c0, r);
}

// ---------------- fp16 row gather ----------------
__device__ __forceinline__ float4 gather_h4(const __half* __restrict__ t, int row, int q) {
    uint2 raw = __ldg((const uint2*)(t + ((size_t)row << 6) + (q << 2)));
    float2 a = __half22float2(*(__half2*)&raw.x);
    float2 b = __half22float2(*(__half2*)&raw.y);
    return make_float4(a.x, a.y, b.x, b.y);
}

#define ACC4(c, v) { acc.x += (c) * (v).x; acc.y += (c) * (v).y; \
                     acc.z += (c) * (v).z; acc.w += (c) * (v).w; }

// Aggregation core, unrolled x8: u = agg_edges(h) + h[node]*dinv^2.
__device__ __forceinline__ float4 agg_core(const __half* __restrict__ t, int node, int q) {
    float di = g_dinv[node];
    float d2 = di * di;
    float4 acc = gather_h4(t, node, q);
    acc.x *= d2; acc.y *= d2; acc.z *= d2; acc.w *= d2;
    int beg = __ldg(&g_off[node]), end = __ldg(&g_off[node + 1]);
    int k = beg;
    for (; k + 8 <= end; k += 8) {
        int2 p0 = __ldg(&g_edges[k]);
        int2 p1 = __ldg(&g_edges[k + 1]);
        int2 p2 = __ldg(&g_edges[k + 2]);
        int2 p3 = __ldg(&g_edges[k + 3]);
        int2 p4 = __ldg(&g_edges[k + 4]);
        int2 p5 = __ldg(&g_edges[k + 5]);
        int2 p6 = __ldg(&g_edges[k + 6]);
        int2 p7 = __ldg(&g_edges[k + 7]);
        float4 v0 = gather_h4(t, p0.x, q);
        float4 v1 = gather_h4(t, p1.x, q);
        float4 v2 = gather_h4(t, p2.x, q);
        float4 v3 = gather_h4(t, p3.x, q);
        float4 v4 = gather_h4(t, p4.x, q);
        float4 v5 = gather_h4(t, p5.x, q);
        float4 v6 = gather_h4(t, p6.x, q);
        float4 v7 = gather_h4(t, p7.x, q);
        ACC4(__int_as_float(p0.y), v0); ACC4(__int_as_float(p1.y), v1);
        ACC4(__int_as_float(p2.y), v2); ACC4(__int_as_float(p3.y), v3);
        ACC4(__int_as_float(p4.y), v4); ACC4(__int_as_float(p5.y), v5);
        ACC4(__int_as_float(p6.y), v6); ACC4(__int_as_float(p7.y), v7);
    }
    if (k + 4 <= end) {
        int2 p0 = __ldg(&g_edges[k]);
        int2 p1 = __ldg(&g_edges[k + 1]);
        int2 p2 = __ldg(&g_edges[k + 2]);
        int2 p3 = __ldg(&g_edges[k + 3]);
        float4 v0 = gather_h4(t, p0.x, q);
        float4 v1 = gather_h4(t, p1.x, q);
        float4 v2 = gather_h4(t, p2.x, q);
        float4 v3 = gather_h4(t, p3.x, q);
        ACC4(__int_as_float(p0.y), v0); ACC4(__int_as_float(p1.y), v1);
        ACC4(__int_as_float(p2.y), v2); ACC4(__int_as_float(p3.y), v3);
        k += 4;
    }
    for (; k < end; k++) {
        int2 p = __ldg(&g_edges[k]);
        float c = __int_as_float(p.y);
        float4 v = gather_h4(t, p.x, q);
        ACC4(c, v);
    }
    return acc;
}

// Warp-level 64x64 matmul: per-node h lives in 16 lanes' float4; broadcast via shfl.
__device__ __forceinline__ float4 warp_matmul(float4 acc, const float* __restrict__ Ws,
                                              const float* __restrict__ bs, int q) {
    float a[4] = {acc.x, acc.y, acc.z, acc.w};
    int c0 = q * 4;
    float4 o = make_float4(bs[c0], bs[c0 + 1], bs[c0 + 2], bs[c0 + 3]);
#pragma unroll
    for (int k = 0; k < HID; k++) {
        float hk = __shfl_sync(0xffffffffu, a[k & 3], k >> 2, 16);
        float4 w = *(const float4*)&Ws[k * HID + c0];
        o.x += hk * w.x; o.y += hk * w.y; o.z += hk * w.z; o.w += hk * w.w;
    }
    o.x = fmaxf(o.x, 0.f); o.y = fmaxf(o.y, 0.f);
    o.z = fmaxf(o.z, 0.f); o.w = fmaxf(o.w, 0.f);
    return o;
}

// ---------------- fused layer: out = relu((agg(h) + h*dinv^2) @ W + b) ----------------
// 512 threads = 32 nodes x 16 lanes; no inter-warp sync after weight load.
__global__ void __launch_bounds__(512) k_layer(const __half* __restrict__ tin,
                                               const float* __restrict__ W,
                                               const float* __restrict__ b,
                                               __half* __restrict__ tout) {
    __shared__ float Ws[HID * HID];
    __shared__ float bs[HID];
    int tid = threadIdx.x;
    for (int i = tid; i < HID * HID; i += 512) Ws[i] = W[i];
    if (tid < HID) bs[tid] = b[tid];
    __syncthreads();
    int q = tid & 15;
    int node = blockIdx.x * 32 + (tid >> 4);
    if (node >= NN) return;
    float4 acc = agg_core(tin, node, q);
    float4 o = warp_matmul(acc, Ws, bs, q);
    store_h4(tout + (size_t)node * HID + q * 4, o);
}

// Layer-3 variant: epilogue goes straight into the mean-pool accumulators.
__global__ void __launch_bounds__(512) k_layer_pool(const __half* __restrict__ tin,
                                                    const float* __restrict__ W,
                                                    const float* __restrict__ b,
                                                    const int* __restrict__ batch) {
    __shared__ float Ws[HID * HID];
    __shared__ float bs[HID];
    int tid = threadIdx.x;
    for (int i = tid; i < HID * HID; i += 512) Ws[i] = W[i];
    if (tid < HID) bs[tid] = b[tid];
    __syncthreads();
    int q = tid & 15;
    int node = blockIdx.x * 32 + (tid >> 4);
    if (node >= NN) return;
    float4 acc = agg_core(tin, node, q);
    float4 o = warp_matmul(acc, Ws, bs, q);
    int g = batch[node];
    red_add_v4(g_pool + (size_t)g * HID + q * 4, o);
    if (q == 0) atomicAdd(&g_cnt[g], 1.0f);
}

// ---------------- per-graph MLP + sigmoid ----------------
__global__ void k_mlp(const float* __restrict__ lw1, const float* __restrict__ lb1,
                      const float* __restrict__ lw2, const float* __restrict__ lb2,
                      float* __restrict__ out) {
    __shared__ float w1s[HID * 32];
    __shared__ float b1s[32];
    __shared__ float w2s[32];
    int tid = threadIdx.x;
    for (int idx = tid; idx < HID * 32; idx += 128) w1s[idx] = lw1[idx];
    if (tid < 32) { b1s[tid] = lb1[tid]; w2s[tid] = lw2[tid]; }
    __syncthreads();
    int g = blockIdx.x * 128 + tid;
    if (g >= NG) return;
    float inv = 1.0f / fmaxf(g_cnt[g], 1.0f);
    float p[HID];
#pragma unroll
    for (int c = 0; c < HID; c++) p[c] = g_pool[g * HID + c] * inv;
    float z = lb2[0];
    for (int j = 0; j < 32; j++) {
        float a = b1s[j];
#pragma unroll
        for (int c = 0; c < HID; c++) a += p[c] * w1s[c * 32 + j];
        a = a > 0.f ? a : 0.f;
        z += a * w2s[j];
    }
    out[g] = 1.0f / (1.0f + expf(-z));
}

extern "C" void kernel_launch(void* const* d_in, const int* in_sizes, int n_in,
                              void* d_out, int out_size) {
    // Size-driven input identification (robust to metadata ordering).
    const float *x = 0, *W1 = 0, *b1 = 0, *W2 = 0, *b2 = 0, *W3 = 0, *b3 = 0;
    const float *lw1 = 0, *lb1 = 0, *lw2 = 0, *lb2 = 0;
    const int *ei = 0, *batch = 0;
    int nW = 0, nb = 0, n32 = 0;
    for (int i = 0; i < n_in; i++) {
        int sz = in_sizes[i];
        const void* p = d_in[i];
        switch (sz) {
            case 300000:  x = (const float*)p; break;
            case 2500000: ei = (const int*)p; break;
            case 150000:  batch = (const int*)p; break;
            case 128:     W1 = (const float*)p; break;
            case 4096:    if (nW++ == 0) W2 = (const float*)p; else W3 = (const float*)p; break;
            case 64:      if (nb == 0) b1 = (const float*)p;
                          else if (nb == 1) b2 = (const float*)p;
                          else b3 = (const float*)p;
                          nb++; break;
            case 2048:    lw1 = (const float*)p; break;
            case 32:      if (n32++ == 0) lb1 = (const float*)p; else lw2 = (const float*)p; break;
            case 1:       lb2 = (const float*)p; break;
        }
    }
    float* out = (float*)d_out;

    __half *gT0, *gT1;
    cudaGetSymbolAddress((void**)&gT0, g_T0);
    cudaGetSymbolAddress((void**)&gT1, g_T1);

    const int TB = 256;
    // init + degree
    k_init     <<<(NG * HID + TB - 1) / TB, TB>>>();
    k_deg_accum<<<(NE + TB - 1) / TB, TB>>>(ei);

    // CSR build (dst-bucketed, packed {src, coef}); dinv fused into ps1
    k_ps1 <<<PS_NB, PS_B>>>();
    k_ps2 <<<1, PS_B>>>();
    k_ps3 <<<PS_NB, PS_B>>>();
    k_fill<<<(NE + TB - 1) / TB, TB>>>(ei);

    // layer 1: aggregate raw x, fused W1+bias+relu -> h1 (fp16)
    k_aggr_x<<<(NN * 16 + TB - 1) / TB, TB>>>(x, W1, b1, gT0);

    // layer 2 fused: h2 = relu((agg(h1)+h1*d2) @ W2 + b2) (fp16)
    k_layer<<<(NN + 31) / 32, 512>>>(gT0, W2, b2, gT1);

    // layer 3 fused + pooled
    k_layer_pool<<<(NN + 31) / 32, 512>>>(gT1, W3, b3, batch);

    // MLP head
    k_mlp<<<(NG + 127) / 128, 128>>>(lw1, lb1, lw2, lb2, out);
}